// round 11
// baseline (speedup 1.0000x reference)
#include <cuda_runtime.h>
#include <cuda_bf16.h>
#include <cstdint>

// Fixed shapes: B=16, T=512, D=384, MAX_LEN=4096
#define LR_B       16
#define LR_T       512
#define LR_D       384
#define LR_ROWB    1536                       // bytes per row
#define LR_D4      96                         // float4 per row
#define LR_MAXLEN  4096
#define LR_NEXP    (LR_B * LR_MAXLEN * LR_D)  // 25,165,824 floats

#define NB_TOK     2048                       // 4 token-warps per block (128 thr)
#define NB_ZERO    8192                       // 8 rows per block

__device__ int g_cum[LR_B * LR_T];
__device__ int g_mel[LR_B];

// ---- async-proxy helpers -------------------------------------------------
__device__ __forceinline__ uint32_t smem_u32(const void* p) {
    return (uint32_t)__cvta_generic_to_shared(p);
}
__device__ __forceinline__ void bulk_s2g(void* gdst, uint32_t ssrc, uint32_t bytes) {
    asm volatile("cp.async.bulk.global.shared::cta.bulk_group [%0], [%1], %2;"
                 :: "l"(gdst), "r"(ssrc), "r"(bytes) : "memory");
}
__device__ __forceinline__ void bulk_commit() {
    asm volatile("cp.async.bulk.commit_group;" ::: "memory");
}
__device__ __forceinline__ void bulk_wait0() {
    asm volatile("cp.async.bulk.wait_group 0;" ::: "memory");
}
__device__ __forceinline__ void fence_async() {
    asm volatile("fence.proxy.async.shared::cta;" ::: "memory");
}

// ---------------------------------------------------------------------------
// Kernel A: shfl-based inclusive scan per batch (3 barriers). Emits mel_lens.
// ---------------------------------------------------------------------------
__global__ void lr_scan_kernel(const int* __restrict__ durations,
                               float* __restrict__ out_tail) {
    __shared__ int wsum[16];
    const int b = blockIdx.x, t = threadIdx.x;
    const int lane = t & 31, warp = t >> 5;

    int v = durations[b * LR_T + t];
    #pragma unroll
    for (int off = 1; off < 32; off <<= 1) {
        int n = __shfl_up_sync(0xffffffffu, v, off);
        if (lane >= off) v += n;
    }
    if (lane == 31) wsum[warp] = v;
    __syncthreads();
    if (warp == 0 && lane < 16) {
        int s = wsum[lane];
        #pragma unroll
        for (int off = 1; off < 16; off <<= 1) {
            int n = __shfl_up_sync(0xffffu, s, off, 16);
            if (lane >= off) s += n;
        }
        wsum[lane] = s;
    }
    __syncthreads();

    g_cum[b * LR_T + t] = v + (warp ? wsum[warp - 1] : 0);
    if (t == 0) {
        const int mel = wsum[15];
        g_mel[b] = mel;
        if (out_tail) out_tail[b] = (float)mel;
    }
}

// ---------------------------------------------------------------------------
// Kernel B: expand via TMA bulk stores. 128 threads = 4 warps.
//  token blocks [0, NB_TOK):   warp = 1 token. Stage row replicated dur
//                              times in SMEM (dur<=7 -> 10752B/warp), then
//                              ONE cp.async.bulk of dur*1536 contiguous bytes.
//  zero blocks  [NB_TOK, ...): 8 rows. Zero 12KB SMEM once; full-tail block
//                              -> ONE 12KB bulk op; boundary -> per-row ops.
// ---------------------------------------------------------------------------
__global__ __launch_bounds__(128)
void lr_expand_kernel(const float4* __restrict__ enc,
                      float*        __restrict__ out) {
    __shared__ float4 stage[4 * 7 * LR_D4];        // 4 warps x 10752 B = 43008 B
    const int warp = threadIdx.x >> 5;
    const int lane = threadIdx.x & 31;

    if (blockIdx.x < NB_TOK) {
        // ---- token path: 1 token per warp ----
        const int tok = blockIdx.x * 4 + warp;     // 0..8191
        const int b   = tok >> 9;
        const int t   = tok & 511;
        const int end   = g_cum[tok];
        const int start = t ? g_cum[tok - 1] : 0;
        const int dur   = end - start;
        if (dur <= 0) return;                      // warp-uniform exit

        const float4* src = enc + (size_t)tok * LR_D4;
        const float4 v0 = src[lane];
        const float4 v1 = src[lane + 32];
        const float4 v2 = src[lane + 64];

        float4* st = stage + warp * (7 * LR_D4);
        for (int p = 0; p < dur; ++p) {            // replicate row in SMEM
            st[p * LR_D4 + lane]      = v0;
            st[p * LR_D4 + lane + 32] = v1;
            st[p * LR_D4 + lane + 64] = v2;
        }
        __syncwarp();
        if (lane == 0) {
            fence_async();
            float* gdst = out + ((size_t)(b << 12) + start) * LR_D;
            bulk_s2g(gdst, smem_u32(st), (uint32_t)(dur * LR_ROWB));
            bulk_commit();
            bulk_wait0();
        }
    } else {
        // ---- zero path: 8 consecutive rows per block ----
        const int r0   = (blockIdx.x - NB_TOK) * 8;
        const int b    = r0 >> 12;
        const int pos0 = r0 & 4095;
        const int mel  = g_mel[b];
        if (pos0 + 8 <= mel) return;               // fully valid: uniform exit

        // zero the first 12288 B of stage (768 float4, 128 threads -> 6 each)
        const float4 z = make_float4(0.f, 0.f, 0.f, 0.f);
        float4* zs = stage;
        #pragma unroll
        for (int i = threadIdx.x; i < 8 * LR_D4; i += 128) zs[i] = z;
        __syncthreads();

        if (pos0 >= mel) {                         // whole 8-row span is tail
            if (threadIdx.x == 0) {
                fence_async();
                bulk_s2g(out + (size_t)r0 * LR_D, smem_u32(zs), 8 * LR_ROWB);
                bulk_commit();
                bulk_wait0();
            }
        } else {                                   // boundary block: per-row
            if (threadIdx.x < 8) {
                const int pos = pos0 + threadIdx.x;
                if (pos >= mel) {
                    fence_async();
                    bulk_s2g(out + (size_t)(r0 + threadIdx.x) * LR_D,
                             smem_u32(zs), LR_ROWB);
                    bulk_commit();
                    bulk_wait0();
                }
            }
        }
    }
}

extern "C" void kernel_launch(void* const* d_in, const int* in_sizes, int n_in,
                              void* d_out, int out_size) {
    const float4* enc = (const float4*)d_in[0];
    const int* durations = (const int*)d_in[1];
    float* out = (float*)d_out;

    float* out_tail = (out_size >= LR_NEXP + LR_B) ? (out + LR_NEXP) : nullptr;

    lr_scan_kernel<<<LR_B, LR_T>>>(durations, out_tail);
    lr_expand_kernel<<<NB_TOK + NB_ZERO, 128>>>(enc, out);
}

// round 12
// speedup vs baseline: 1.0783x; 1.0783x over previous
#include <cuda_runtime.h>
#include <cuda_bf16.h>
#include <cstdint>

// Fixed shapes: B=16, T=512, D=384, MAX_LEN=4096
#define LR_B       16
#define LR_T       512
#define LR_D4      96                        // float4 per row
#define LR_MAXLEN  4096
#define LR_NEXP    (LR_B * LR_MAXLEN * 384)  // 25,165,824 floats

#define NTOK_BLK   1024                      // 8 token-warps per block
#define NZERO_BLK  8192                      // 8 zero-rows per block

__device__ int g_cum[LR_B * LR_T];
__device__ int g_mel[LR_B];

// ---------------------------------------------------------------------------
// Kernel A (primary): shfl-based inclusive scan per batch (3 barriers).
// Calls cudaTriggerProgrammaticLaunchCompletion() as soon as its global
// writes are issued so the PDL-launched expand can pass its grid sync early.
// ---------------------------------------------------------------------------
__global__ void lr_scan_kernel(const int* __restrict__ durations,
                               float* __restrict__ out_tail) {
    __shared__ int wsum[16];
    const int b = blockIdx.x, t = threadIdx.x;
    const int lane = t & 31, warp = t >> 5;

    int v = durations[b * LR_T + t];
    #pragma unroll
    for (int off = 1; off < 32; off <<= 1) {
        int n = __shfl_up_sync(0xffffffffu, v, off);
        if (lane >= off) v += n;
    }
    if (lane == 31) wsum[warp] = v;
    __syncthreads();
    if (warp == 0 && lane < 16) {
        int s = wsum[lane];
        #pragma unroll
        for (int off = 1; off < 16; off <<= 1) {
            int n = __shfl_up_sync(0xffffu, s, off, 16);
            if (lane >= off) s += n;
        }
        wsum[lane] = s;
    }
    __syncthreads();

    g_cum[b * LR_T + t] = v + (warp ? wsum[warp - 1] : 0);
    if (t == 0) {
        const int mel = wsum[15];
        g_mel[b] = mel;
        if (out_tail) out_tail[b] = (float)mel;
    }
    cudaTriggerProgrammaticLaunchCompletion();
}

// ---------------------------------------------------------------------------
// Kernel B (secondary, PDL): exact R2 expand structure (the measured-best
// 16.7us body). Scan-independent work (indices + enc row loads) is issued
// BEFORE cudaGridDependencySynchronize(); g_cum/g_mel reads after it.
// ---------------------------------------------------------------------------
__global__ __launch_bounds__(256)
void lr_expand_kernel(const float4* __restrict__ enc,
                      float4*       __restrict__ out) {
    const int warp = threadIdx.x >> 5;
    const int lane = threadIdx.x & 31;

    if (blockIdx.x < NTOK_BLK) {
        // ---- token path: 1 token per warp ----
        const int tok = blockIdx.x * 8 + warp;        // 0..8191
        const int b   = tok >> 9;
        const int t   = tok & 511;

        // scan-independent: start the enc row loads now
        const float4* src = enc + (size_t)tok * LR_D4;
        const float4 v0 = src[lane];
        const float4 v1 = src[lane + 32];
        const float4 v2 = src[lane + 64];

        cudaGridDependencySynchronize();              // wait for scan results

        const int end   = g_cum[tok];
        const int start = t ? g_cum[tok - 1] : 0;
        if (start >= end) return;                     // dur == 0

        float4* dst = out + ((size_t)(b << 12) + start) * LR_D4;
        for (int p = start; p < end; ++p, dst += LR_D4) {
            dst[lane]      = v0;
            dst[lane + 32] = v1;
            dst[lane + 64] = v2;
        }
    } else {
        // ---- zero path: 1 row per warp ----
        const int row = (blockIdx.x - NTOK_BLK) * 8 + warp;   // 0..65535
        const int b   = row >> 12;
        const int pos = row & 4095;

        cudaGridDependencySynchronize();              // wait for g_mel

        if (pos < g_mel[b]) return;                   // token warps own it

        const float4 z = make_float4(0.f, 0.f, 0.f, 0.f);
        float4* dst = out + (size_t)row * LR_D4;
        dst[lane]      = z;
        dst[lane + 32] = z;
        dst[lane + 64] = z;
    }
}

extern "C" void kernel_launch(void* const* d_in, const int* in_sizes, int n_in,
                              void* d_out, int out_size) {
    const float4* enc = (const float4*)d_in[0];
    const int* durations = (const int*)d_in[1];
    float* out = (float*)d_out;

    float* out_tail = (out_size >= LR_NEXP + LR_B) ? (out + LR_NEXP) : nullptr;

    // Primary: plain launch
    lr_scan_kernel<<<LR_B, LR_T>>>(durations, out_tail);

    // Secondary: programmatic dependent launch (overlaps with primary;
    // in-kernel griddepcontrol.wait provides the ordering).
    cudaLaunchConfig_t cfg = {};
    cfg.gridDim  = dim3(NTOK_BLK + NZERO_BLK);
    cfg.blockDim = dim3(256);
    cudaLaunchAttribute attr[1];
    attr[0].id = cudaLaunchAttributeProgrammaticStreamSerialization;
    attr[0].val.programmaticStreamSerializationAllowed = 1;
    cfg.attrs = attr;
    cfg.numAttrs = 1;
    cudaLaunchKernelEx(&cfg, lr_expand_kernel, enc, (float4*)out);
}